// round 15
// baseline (speedup 1.0000x reference)
#include <cuda_runtime.h>
#include <cuda_bf16.h>
#include <cstdint>

// ============================================================================
// QLV4 Linear — FINAL SEMANTICS (over-determined by R13/R14 fingerprints):
//   out = f32( bf16( sum_k  bf16(x[m,k]) * bf16(w[n,k]) ) )   f32 accumulate
//   w[n,k] = (q - zp) * sc  (f32), group = flat/128
// Pass 1: x f32 -> bf16.  Pass 2: dequant -> bf16.  Pass 3: bf16 HMMA GEMM
// (cp.async 3-stage, BK=64, formula LDS fragments, m16n8k16.bf16),
// epilogue rounds accumulators through bf16 (matches reference exactly up to
// f32 accumulation order ~1e-6).
// ============================================================================

#define M_TOTAL 1024
#define N_TOTAL 8192
#define K_TOTAL 8192
#define BM 128
#define BN 128
#define BK 64
#define KT (K_TOTAL / BK)
#define STAGES 3
#define THREADS 256
#define A_STAGE_BYTES (BM * BK * 2)
#define B_STAGE_BYTES (BN * BK * 2)
#define STAGE_BYTES (A_STAGE_BYTES + B_STAGE_BYTES)
#define SMEM_TOTAL (STAGES * STAGE_BYTES)             // 98304
#define W_ELEMS ((size_t)N_TOTAL * K_TOTAL)
#define X_ELEMS ((size_t)M_TOTAL * K_TOTAL)

// bf16 scratch: weights (128 MB), x (16 MB); uint4 => 16B aligned
__device__ uint4 g_wb4[W_ELEMS / 8];
__device__ uint4 g_xb4[X_ELEMS / 8];

// ---------------------------------------------------------------------------
__device__ __forceinline__ uint32_t smem_u32(const void* p) {
    uint32_t a;
    asm("{ .reg .u64 t; cvta.to.shared.u64 t, %1; cvt.u32.u64 %0, t; }"
        : "=r"(a) : "l"(p));
    return a;
}

__device__ __forceinline__ void cp_async16(uint32_t dst, const void* src) {
    asm volatile("cp.async.cg.shared.global [%0], [%1], 16;"
                 :: "r"(dst), "l"(src) : "memory");
}

__device__ __forceinline__ void cp_commit() {
    asm volatile("cp.async.commit_group;" ::: "memory");
}

template <int N>
__device__ __forceinline__ void cp_wait() {
    asm volatile("cp.async.wait_group %0;" :: "n"(N) : "memory");
}

__device__ __forceinline__ uint32_t lds_b32(uint32_t addr) {
    uint32_t v;
    asm volatile("ld.shared.b32 %0, [%1];" : "=r"(v) : "r"(addr));
    return v;
}

__device__ __forceinline__ void mma_bf16(float* d, const uint32_t* a,
                                         uint32_t b0, uint32_t b1) {
    asm volatile(
        "mma.sync.aligned.m16n8k16.row.col.f32.bf16.bf16.f32 "
        "{%0,%1,%2,%3}, {%4,%5,%6,%7}, {%8,%9}, {%0,%1,%2,%3};"
        : "+f"(d[0]), "+f"(d[1]), "+f"(d[2]), "+f"(d[3])
        : "r"(a[0]), "r"(a[1]), "r"(a[2]), "r"(a[3]), "r"(b0), "r"(b1));
}

__device__ __forceinline__ uint32_t pack_bf2(float a, float b) {
    __nv_bfloat162 t;
    t.x = __float2bfloat16_rn(a);
    t.y = __float2bfloat16_rn(b);
    return *(uint32_t*)&t;
}

__device__ __forceinline__ float bf16_round(float x) {
    return __bfloat162float(__float2bfloat16_rn(x));
}

__device__ __forceinline__ uint32_t sw_addr(uint32_t tile, int row, int kcol) {
    const uint32_t chunk = (uint32_t)(kcol >> 3);
    return tile + (uint32_t)row * 128 +
           (((chunk ^ ((uint32_t)row & 7u))) << 4) + ((uint32_t)(kcol & 7) * 2);
}

// ---------------------------------------------------------------------------
// Pass 1: x f32 -> bf16 (the reference's bf16(x) operand rounding)
// ---------------------------------------------------------------------------
__global__ void __launch_bounds__(256)
convx_kernel(const float* __restrict__ X) {
    const size_t t = (size_t)blockIdx.x * 256 + threadIdx.x;
    const size_t base = t * 8;
    const float4 a = *(const float4*)(X + base);
    const float4 b = *(const float4*)(X + base + 4);
    uint4 o;
    o.x = pack_bf2(a.x, a.y);
    o.y = pack_bf2(a.z, a.w);
    o.z = pack_bf2(b.x, b.y);
    o.w = pack_bf2(b.z, b.w);
    g_xb4[t] = o;
}

// ---------------------------------------------------------------------------
// Pass 2: dequant codes -> bf16 w. w = (q - zp)*sc (f32) -> bf16, grp = flat/128
// ---------------------------------------------------------------------------
__global__ void __launch_bounds__(256)
dequant_kernel(const float* __restrict__ WQ, const float* __restrict__ SC,
               const float* __restrict__ ZP) {
    const size_t t = (size_t)blockIdx.x * 256 + threadIdx.x;
    const size_t base = t * 8;
    const int g = (int)(base >> 7);
    const float sc = __ldg(SC + g);
    const float zp = __ldg(ZP + g);
    const float4 q0 = *(const float4*)(WQ + base);
    const float4 q1 = *(const float4*)(WQ + base + 4);
    uint4 o;
    o.x = pack_bf2((q0.x - zp) * sc, (q0.y - zp) * sc);
    o.y = pack_bf2((q0.z - zp) * sc, (q0.w - zp) * sc);
    o.z = pack_bf2((q1.x - zp) * sc, (q1.y - zp) * sc);
    o.w = pack_bf2((q1.z - zp) * sc, (q1.w - zp) * sc);
    g_wb4[t] = o;
}

// ---------------------------------------------------------------------------
// Pass 3: GEMM. CTA tile 128x128xBK64, warps 2(M)x4(N), warp tile 64x32.
// ---------------------------------------------------------------------------
__global__ void __launch_bounds__(THREADS, 2)
gemm_kernel(float* __restrict__ OUT) {
    extern __shared__ char smem[];
    const uint32_t sbase = smem_u32(smem);

    const int tid = threadIdx.x;
    const int l = tid & 31;
    const int w = tid >> 5;
    const int wm = w & 1;
    const int wn = w >> 1;
    const int mBase = blockIdx.x * BM;   // x-fastest: share B strip in L2
    const int nBase = blockIdx.y * BN;

    const __nv_bfloat16* Ag = (const __nv_bfloat16*)g_xb4 + (size_t)mBase * K_TOTAL;
    const __nv_bfloat16* Bg = (const __nv_bfloat16*)g_wb4 + (size_t)nBase * K_TOTAL;

    const int lrow = tid >> 3;
    const int lcol = tid & 7;
    const int gID = l >> 2;
    const int tig = l & 3;

    float acc[4][4][4];
    #pragma unroll
    for (int i = 0; i < 4; i++)
        #pragma unroll
        for (int j = 0; j < 4; j++)
            #pragma unroll
            for (int c = 0; c < 4; c++) acc[i][j][c] = 0.f;

    auto load_stage = [&](int kt, int slot) {
        const uint32_t sa = sbase + slot * STAGE_BYTES;
        const uint32_t sb = sa + A_STAGE_BYTES;
        const __nv_bfloat16* ga = Ag + kt * BK + lcol * 8;
        const __nv_bfloat16* gb = Bg + kt * BK + lcol * 8;
        #pragma unroll
        for (int i = 0; i < 4; i++) {
            const int r = lrow + i * 32;
            const uint32_t phys = ((uint32_t)(lcol ^ (r & 7))) << 4;
            cp_async16(sa + r * 128 + phys, ga + (size_t)r * K_TOTAL);
            cp_async16(sb + r * 128 + phys, gb + (size_t)r * K_TOTAL);
        }
    };

    #pragma unroll
    for (int s = 0; s < STAGES - 1; s++) {
        load_stage(s, s);
        cp_commit();
    }

    for (int kt = 0; kt < KT; kt++) {
        cp_wait<STAGES - 2>();
        __syncthreads();

        const int nk = kt + STAGES - 1;
        if (nk < KT) load_stage(nk, nk % STAGES);
        cp_commit();

        const int slot = kt % STAGES;
        const uint32_t sa = sbase + slot * STAGE_BYTES;
        const uint32_t sb = sa + A_STAGE_BYTES;

        #pragma unroll
        for (int ks = 0; ks < 4; ks++) {
            const int kc = ks * 16 + tig * 2;
            uint32_t afr[4][4];
            #pragma unroll
            for (int mi = 0; mi < 4; mi++) {
                const int r0 = wm * 64 + mi * 16 + gID;
                afr[mi][0] = lds_b32(sw_addr(sa, r0,     kc));
                afr[mi][1] = lds_b32(sw_addr(sa, r0 + 8, kc));
                afr[mi][2] = lds_b32(sw_addr(sa, r0,     kc + 8));
                afr[mi][3] = lds_b32(sw_addr(sa, r0 + 8, kc + 8));
            }
            uint32_t bfr[4][2];
            #pragma unroll
            for (int ni = 0; ni < 4; ni++) {
                const int nr = wn * 32 + ni * 8 + gID;
                bfr[ni][0] = lds_b32(sw_addr(sb, nr, kc));
                bfr[ni][1] = lds_b32(sw_addr(sb, nr, kc + 8));
            }
            #pragma unroll
            for (int mi = 0; mi < 4; mi++)
                #pragma unroll
                for (int ni = 0; ni < 4; ni++)
                    mma_bf16(acc[mi][ni], afr[mi], bfr[ni][0], bfr[ni][1]);
        }
    }

    // Epilogue: round through bf16 (reference: bf16 einsum result -> f32)
    const int m0 = mBase + wm * 64 + gID;
    const int n0 = nBase + wn * 32 + tig * 2;
    #pragma unroll
    for (int mi = 0; mi < 4; mi++) {
        #pragma unroll
        for (int ni = 0; ni < 4; ni++) {
            float2 v0, v1;
            v0.x = bf16_round(acc[mi][ni][0]);
            v0.y = bf16_round(acc[mi][ni][1]);
            v1.x = bf16_round(acc[mi][ni][2]);
            v1.y = bf16_round(acc[mi][ni][3]);
            const size_t r0 = (size_t)(m0 + mi * 16) * N_TOTAL + (n0 + ni * 8);
            const size_t r1 = r0 + 8 * N_TOTAL;
            *(float2*)(OUT + r0) = v0;
            *(float2*)(OUT + r1) = v1;
        }
    }
}

// ---------------------------------------------------------------------------
extern "C" void kernel_launch(void* const* d_in, const int* in_sizes, int n_in,
                              void* d_out, int out_size) {
    // metadata.txt order: input(f32), weight_q, weight_scale, weight_zero_point
    const float* X  = (const float*)d_in[0];
    const float* WQ = (const float*)d_in[1];
    const float* SC = (const float*)d_in[2];
    const float* ZP = (const float*)d_in[3];
    float* OUT = (float*)d_out;

    cudaFuncSetAttribute(gemm_kernel,
                         cudaFuncAttributeMaxDynamicSharedMemorySize,
                         SMEM_TOTAL);

    convx_kernel<<<(int)(X_ELEMS / (8 * 256)), 256>>>(X);
    dequant_kernel<<<(int)(W_ELEMS / (8 * 256)), 256>>>(WQ, SC, ZP);

    dim3 grid(M_TOTAL / BM, N_TOTAL / BN);   // (8, 64)
    gemm_kernel<<<grid, THREADS, SMEM_TOTAL>>>(OUT);
}

// round 16
// speedup vs baseline: 1.0952x; 1.0952x over previous
#include <cuda_runtime.h>
#include <cuda_bf16.h>
#include <cstdint>

// ============================================================================
// QLV4 Linear (semantics locked R15, PASS):
//   out = f32(bf16( sum_k bf16(x)*bf16((q-zp)*sc) ))  [f32 accum]
// R16: GEMM fragment loads via ldmatrix.x4 (6 LDSM vs 24 LDS per k16-step),
// dequant with 16 elems/thread. Pipeline unchanged (3-stage cp.async, BK=64).
// ============================================================================

#define M_TOTAL 1024
#define N_TOTAL 8192
#define K_TOTAL 8192
#define BM 128
#define BN 128
#define BK 64
#define KT (K_TOTAL / BK)
#define STAGES 3
#define THREADS 256
#define A_STAGE_BYTES (BM * BK * 2)
#define B_STAGE_BYTES (BN * BK * 2)
#define STAGE_BYTES (A_STAGE_BYTES + B_STAGE_BYTES)
#define SMEM_TOTAL (STAGES * STAGE_BYTES)             // 98304
#define W_ELEMS ((size_t)N_TOTAL * K_TOTAL)
#define X_ELEMS ((size_t)M_TOTAL * K_TOTAL)

__device__ uint4 g_wb4[W_ELEMS / 8];
__device__ uint4 g_xb4[X_ELEMS / 8];

// ---------------------------------------------------------------------------
__device__ __forceinline__ uint32_t smem_u32(const void* p) {
    uint32_t a;
    asm("{ .reg .u64 t; cvta.to.shared.u64 t, %1; cvt.u32.u64 %0, t; }"
        : "=r"(a) : "l"(p));
    return a;
}

__device__ __forceinline__ void cp_async16(uint32_t dst, const void* src) {
    asm volatile("cp.async.cg.shared.global [%0], [%1], 16;"
                 :: "r"(dst), "l"(src) : "memory");
}

__device__ __forceinline__ void cp_commit() {
    asm volatile("cp.async.commit_group;" ::: "memory");
}

template <int N>
__device__ __forceinline__ void cp_wait() {
    asm volatile("cp.async.wait_group %0;" :: "n"(N) : "memory");
}

__device__ __forceinline__ void ldsm_x4(uint32_t* r, uint32_t addr) {
    asm volatile("ldmatrix.sync.aligned.m8n8.x4.shared.b16 {%0,%1,%2,%3}, [%4];"
                 : "=r"(r[0]), "=r"(r[1]), "=r"(r[2]), "=r"(r[3])
                 : "r"(addr));
}

__device__ __forceinline__ void mma_bf16(float* d, const uint32_t* a,
                                         uint32_t b0, uint32_t b1) {
    asm volatile(
        "mma.sync.aligned.m16n8k16.row.col.f32.bf16.bf16.f32 "
        "{%0,%1,%2,%3}, {%4,%5,%6,%7}, {%8,%9}, {%0,%1,%2,%3};"
        : "+f"(d[0]), "+f"(d[1]), "+f"(d[2]), "+f"(d[3])
        : "r"(a[0]), "r"(a[1]), "r"(a[2]), "r"(a[3]), "r"(b0), "r"(b1));
}

__device__ __forceinline__ uint32_t pack_bf2(float a, float b) {
    __nv_bfloat162 t;
    t.x = __float2bfloat16_rn(a);
    t.y = __float2bfloat16_rn(b);
    return *(uint32_t*)&t;
}

__device__ __forceinline__ float bf16_round(float x) {
    return __bfloat162float(__float2bfloat16_rn(x));
}

// chunk-level swizzled address (kchunk = kcol/8)
__device__ __forceinline__ uint32_t sw_chunk(uint32_t tile, int row, int kchunk) {
    return tile + (uint32_t)row * 128 +
           ((((uint32_t)kchunk ^ ((uint32_t)row & 7u))) << 4);
}

// ---------------------------------------------------------------------------
// Pass 1: x f32 -> bf16, 16 elems/thread (MLP>=4 overlaps PTW + latency)
// ---------------------------------------------------------------------------
__global__ void __launch_bounds__(256)
convx_kernel(const float* __restrict__ X) {
    const size_t t = (size_t)blockIdx.x * 256 + threadIdx.x;
    const size_t base = t * 16;
    const float4 a0 = *(const float4*)(X + base);
    const float4 a1 = *(const float4*)(X + base + 4);
    const float4 a2 = *(const float4*)(X + base + 8);
    const float4 a3 = *(const float4*)(X + base + 12);
    uint4 o0, o1;
    o0.x = pack_bf2(a0.x, a0.y); o0.y = pack_bf2(a0.z, a0.w);
    o0.z = pack_bf2(a1.x, a1.y); o0.w = pack_bf2(a1.z, a1.w);
    o1.x = pack_bf2(a2.x, a2.y); o1.y = pack_bf2(a2.z, a2.w);
    o1.z = pack_bf2(a3.x, a3.y); o1.w = pack_bf2(a3.z, a3.w);
    g_xb4[t * 2] = o0;
    g_xb4[t * 2 + 1] = o1;
}

// ---------------------------------------------------------------------------
// Pass 2: dequant -> bf16, 16 elems/thread (one 128-elem group per 8 threads)
// ---------------------------------------------------------------------------
__global__ void __launch_bounds__(256)
dequant_kernel(const float* __restrict__ WQ, const float* __restrict__ SC,
               const float* __restrict__ ZP) {
    const size_t t = (size_t)blockIdx.x * 256 + threadIdx.x;
    const size_t base = t * 16;
    const int g = (int)(base >> 7);
    const float sc = __ldg(SC + g);
    const float nzs = -__ldg(ZP + g) * sc;
    uint4 o0, o1;
    {
        const float4 q0 = *(const float4*)(WQ + base);
        const float4 q1 = *(const float4*)(WQ + base + 4);
        o0.x = pack_bf2(fmaf(q0.x, sc, nzs), fmaf(q0.y, sc, nzs));
        o0.y = pack_bf2(fmaf(q0.z, sc, nzs), fmaf(q0.w, sc, nzs));
        o0.z = pack_bf2(fmaf(q1.x, sc, nzs), fmaf(q1.y, sc, nzs));
        o0.w = pack_bf2(fmaf(q1.z, sc, nzs), fmaf(q1.w, sc, nzs));
    }
    {
        const float4 q2 = *(const float4*)(WQ + base + 8);
        const float4 q3 = *(const float4*)(WQ + base + 12);
        o1.x = pack_bf2(fmaf(q2.x, sc, nzs), fmaf(q2.y, sc, nzs));
        o1.y = pack_bf2(fmaf(q2.z, sc, nzs), fmaf(q2.w, sc, nzs));
        o1.z = pack_bf2(fmaf(q3.x, sc, nzs), fmaf(q3.y, sc, nzs));
        o1.w = pack_bf2(fmaf(q3.z, sc, nzs), fmaf(q3.w, sc, nzs));
    }
    g_wb4[t * 2] = o0;
    g_wb4[t * 2 + 1] = o1;
}

// ---------------------------------------------------------------------------
// Pass 3: GEMM. CTA 128x128xBK64, warps 2(M)x4(N), warp tile 64x32.
// Fragments via ldmatrix.x4 (geometry verified consistent in R2/R4 bisects).
// ---------------------------------------------------------------------------
__global__ void __launch_bounds__(THREADS, 2)
gemm_kernel(float* __restrict__ OUT) {
    extern __shared__ char smem[];
    const uint32_t sbase = smem_u32(smem);

    const int tid = threadIdx.x;
    const int l = tid & 31;
    const int w = tid >> 5;
    const int wm = w & 1;
    const int wn = w >> 1;
    const int mBase = blockIdx.x * BM;   // x-fastest: share B strip in L2
    const int nBase = blockIdx.y * BN;

    const __nv_bfloat16* Ag = (const __nv_bfloat16*)g_xb4 + (size_t)mBase * K_TOTAL;
    const __nv_bfloat16* Bg = (const __nv_bfloat16*)g_wb4 + (size_t)nBase * K_TOTAL;

    const int lrow = tid >> 3;
    const int lcol = tid & 7;
    const int gID = l >> 2;
    const int tig = l & 3;

    // ldmatrix lane geometry (proven layout):
    // A x4: m16k16 -> R0=(r,k0) R1=(r+8,k0) R2=(r,k8) R3=(r+8,k8)
    const int a_rin = ((l >> 3) & 1) * 8 + (l & 7);
    const int a_ks = l >> 4;
    // B x4: two n8k16 groups -> R0=b0(n0) R1=b1(n0) R2=b0(n1) R3=b1(n1)
    const int b_rin = (l >> 4) * 8 + (l & 7);
    const int b_ks = (l >> 3) & 1;

    float acc[4][4][4];
    #pragma unroll
    for (int i = 0; i < 4; i++)
        #pragma unroll
        for (int j = 0; j < 4; j++)
            #pragma unroll
            for (int c = 0; c < 4; c++) acc[i][j][c] = 0.f;

    auto load_stage = [&](int kt, int slot) {
        const uint32_t sa = sbase + slot * STAGE_BYTES;
        const uint32_t sb = sa + A_STAGE_BYTES;
        const __nv_bfloat16* ga = Ag + kt * BK + lcol * 8;
        const __nv_bfloat16* gb = Bg + kt * BK + lcol * 8;
        #pragma unroll
        for (int i = 0; i < 4; i++) {
            const int r = lrow + i * 32;
            const uint32_t phys = ((uint32_t)(lcol ^ (r & 7))) << 4;
            cp_async16(sa + r * 128 + phys, ga + (size_t)r * K_TOTAL);
            cp_async16(sb + r * 128 + phys, gb + (size_t)r * K_TOTAL);
        }
    };

    #pragma unroll
    for (int s = 0; s < STAGES - 1; s++) {
        load_stage(s, s);
        cp_commit();
    }

    for (int kt = 0; kt < KT; kt++) {
        cp_wait<STAGES - 2>();
        __syncthreads();

        const int nk = kt + STAGES - 1;
        if (nk < KT) load_stage(nk, nk % STAGES);
        cp_commit();

        const int slot = kt % STAGES;
        const uint32_t sa = sbase + slot * STAGE_BYTES;
        const uint32_t sb = sa + A_STAGE_BYTES;

        #pragma unroll
        for (int ks = 0; ks < 4; ks++) {
            uint32_t afr[4][4];
            #pragma unroll
            for (int mi = 0; mi < 4; mi++) {
                const int row = wm * 64 + mi * 16 + a_rin;
                ldsm_x4(afr[mi], sw_chunk(sa, row, ks * 2 + a_ks));
            }
            uint32_t bfr[2][4];
            #pragma unroll
            for (int j = 0; j < 2; j++) {
                const int row = wn * 32 + j * 16 + b_rin;
                ldsm_x4(bfr[j], sw_chunk(sb, row, ks * 2 + b_ks));
            }
            #pragma unroll
            for (int mi = 0; mi < 4; mi++)
                #pragma unroll
                for (int ni = 0; ni < 4; ni++)
                    mma_bf16(acc[mi][ni], afr[mi],
                             bfr[ni >> 1][(ni & 1) * 2],
                             bfr[ni >> 1][(ni & 1) * 2 + 1]);
        }
    }

    // Epilogue: round through bf16 (reference grid)
    const int m0 = mBase + wm * 64 + gID;
    const int n0 = nBase + wn * 32 + tig * 2;
    #pragma unroll
    for (int mi = 0; mi < 4; mi++) {
        #pragma unroll
        for (int ni = 0; ni < 4; ni++) {
            float2 v0, v1;
            v0.x = bf16_round(acc[mi][ni][0]);
            v0.y = bf16_round(acc[mi][ni][1]);
            v1.x = bf16_round(acc[mi][ni][2]);
            v1.y = bf16_round(acc[mi][ni][3]);
            const size_t r0 = (size_t)(m0 + mi * 16) * N_TOTAL + (n0 + ni * 8);
            const size_t r1 = r0 + 8 * N_TOTAL;
            *(float2*)(OUT + r0) = v0;
            *(float2*)(OUT + r1) = v1;
        }
    }
}

// ---------------------------------------------------------------------------
extern "C" void kernel_launch(void* const* d_in, const int* in_sizes, int n_in,
                              void* d_out, int out_size) {
    const float* X  = (const float*)d_in[0];
    const float* WQ = (const float*)d_in[1];
    const float* SC = (const float*)d_in[2];
    const float* ZP = (const float*)d_in[3];
    float* OUT = (float*)d_out;

    cudaFuncSetAttribute(gemm_kernel,
                         cudaFuncAttributeMaxDynamicSharedMemorySize,
                         SMEM_TOTAL);

    convx_kernel<<<(int)(X_ELEMS / (16 * 256)), 256>>>(X);
    dequant_kernel<<<(int)(W_ELEMS / (16 * 256)), 256>>>(WQ, SC, ZP);

    dim3 grid(M_TOTAL / BM, N_TOTAL / BN);   // (8, 64)
    gemm_kernel<<<grid, THREADS, SMEM_TOTAL>>>(OUT);
}